// round 1
// baseline (speedup 1.0000x reference)
#include <cuda_runtime.h>
#include <math.h>

// LogSparseAttention: B=2, L=S=2048, H=8, E=D=64.
// Mask structure (derived from reference _row_mask with sub_len=win_len=2048, log_l=11):
//   row r < 22  : attends cols 0..r                       (r+1 <= 22 cols)
//   row r >= 22 : attends cols {r-10..r} U {r-10-2^i, i=0..10, if >=0}  (<= 22 cols)
// => gather-attention with <=22 keys per query row.

#define BB 2
#define LL 2048
#define HH 8
#define EE 64
#define DD 64
#define QSCALE 0.125f  // 1/sqrt(64)

__global__ __launch_bounds__(256, 8)
void logsparse_attn_kernel(const float* __restrict__ Q,
                           const float* __restrict__ K,
                           const float* __restrict__ V,
                           float* __restrict__ O)
{
    __shared__ float sq[8][EE];  // one q row per warp

    const int warp = threadIdx.x >> 5;
    const int lane = threadIdx.x & 31;
    const int row  = blockIdx.x * 8 + warp;          // row over (b, l, h), Q-layout order
    // Q layout (B, L, H, E): row = (b*L + l)*H + h
    const int b = row / (LL * HH);
    const int rem = row - b * (LL * HH);
    const int l = rem / HH;
    const int h = rem - l * HH;

    // ---- stage q into shared (2 floats per lane) ----
    const float* qrow = Q + (size_t)row * EE;
    sq[warp][lane]      = qrow[lane];
    sq[warp][lane + 32] = qrow[lane + 32];
    __syncwarp();

    // ---- per-lane column index for this query row ----
    int col = 0;
    bool active = false;
    if (l < 22) {
        if (lane <= l) { col = lane; active = true; }
    } else {
        if (lane <= 10) {
            int c = l - 10 - (1 << (10 - lane));   // log terms, ascending
            if (c >= 0) { col = c; active = true; }
        } else if (lane <= 21) {
            col = l - 21 + lane;                   // local window r-10..r
            active = true;
        }
    }

    // ---- score: each active lane computes dot(q, K[col]) ----
    float s = -INFINITY;
    if (active) {
        const float4* kp = (const float4*)(K + ((((size_t)b * LL + col) * HH + h) * EE));
        const float4* qp = (const float4*)sq[warp];
        float acc = 0.0f;
#pragma unroll
        for (int i = 0; i < EE / 4; ++i) {
            float4 kk = kp[i];
            float4 qq = qp[i];
            acc += kk.x * qq.x + kk.y * qq.y + kk.z * qq.z + kk.w * qq.w;
        }
        s = acc * QSCALE;
    }

    // ---- warp softmax over <=22 active lanes ----
    float m = s;
#pragma unroll
    for (int o = 16; o; o >>= 1) m = fmaxf(m, __shfl_xor_sync(0xffffffffu, m, o));
    float p = active ? __expf(s - m) : 0.0f;
    float sum = p;
#pragma unroll
    for (int o = 16; o; o >>= 1) sum += __shfl_xor_sync(0xffffffffu, sum, o);
    p *= __frcp_rn(sum);

    // ---- output: lane = dim; loop over keys via shuffle broadcast ----
    float acc0 = 0.0f, acc1 = 0.0f;
#pragma unroll
    for (int j = 0; j < 22; ++j) {
        float pj = __shfl_sync(0xffffffffu, p, j);
        int   cj = __shfl_sync(0xffffffffu, col, j);
        if (pj > 0.0f) {  // warp-uniform branch: skips inactive keys with no divergence
            const float* vp = V + ((((size_t)b * LL + cj) * HH + h) * DD);
            acc0 = fmaf(pj, vp[lane],      acc0);
            acc1 = fmaf(pj, vp[lane + 32], acc1);
        }
    }

    float* op = O + (size_t)row * DD;   // O layout (B, L, H, D) == row-major over same row index
    op[lane]      = acc0;
    op[lane + 32] = acc1;
}

extern "C" void kernel_launch(void* const* d_in, const int* in_sizes, int n_in,
                              void* d_out, int out_size) {
    const float* Q = (const float*)d_in[0];
    const float* K = (const float*)d_in[1];
    const float* V = (const float*)d_in[2];
    // d_in[3] = attention_mask (unused by reference math)
    float* O = (float*)d_out;

    const int total_rows = BB * LL * HH;       // 32768 warps
    dim3 grid(total_rows / 8);                 // 8 warps (256 threads) per block
    logsparse_attn_kernel<<<grid, 256>>>(Q, K, V, O);
}

// round 2
// speedup vs baseline: 2.3431x; 2.3431x over previous
#include <cuda_runtime.h>
#include <math.h>

// LogSparseAttention: B=2, L=S=2048, H=8, E=D=64.
// Mask: row l<22 attends cols 0..l; row l>=22 attends {l-10..l} U {l-10-2^i, i=0..10, >=0}.
// <=22 keys per query row -> gather attention.
// R2: fully line-coalesced gathers. Score phase: 8 lanes/key, 4 keys/iter.
//     V phase: 16 lanes/key, 2 keys/iter. All LDG.128 touch whole 128B lines.

#define BB 2
#define LL 2048
#define HH 8
#define EE 64
#define DD 64
#define QSCALE 0.125f  // 1/sqrt(64)
#define FULL 0xffffffffu

// Clamped column index for key slot j of query row l (valid >=0 even if inactive).
__device__ __forceinline__ int col_of(int l, int j) {
    int c;
    if (l < 22) {
        c = (j <= l) ? j : 0;
    } else if (j <= 10) {
        int sh = (10 - j) & 31;            // shift amt only meaningful when j<=10
        c = l - 10 - (1 << sh);
        c = (c >= 0) ? c : 0;
    } else if (j <= 21) {
        c = l - 21 + j;                    // local window l-10..l
    } else {
        c = 0;
    }
    return c;
}

__device__ __forceinline__ bool act_of(int l, int j) {
    if (j > 21) return false;
    if (l < 22) return j <= l;
    if (j <= 10) return (l - 10 - (1 << ((10 - j) & 31))) >= 0;
    return true;
}

__global__ __launch_bounds__(256, 8)
void logsparse_attn_kernel(const float* __restrict__ Q,
                           const float* __restrict__ K,
                           const float* __restrict__ V,
                           float* __restrict__ O)
{
    __shared__ float sq[8][EE];   // one scaled q row per warp

    const int warp = threadIdx.x >> 5;
    const int lane = threadIdx.x & 31;
    const int row  = blockIdx.x * 8 + warp;        // (b*L + l)*H + h
    const int b    = row / (LL * HH);
    const int rem  = row - b * (LL * HH);
    const int l    = rem / HH;
    const int h    = rem - l * HH;

    // stage scaled q (coalesced)
    const float* qrow = Q + (size_t)row * EE;
    sq[warp][lane]      = qrow[lane]      * QSCALE;
    sq[warp][lane + 32] = qrow[lane + 32] * QSCALE;
    __syncwarp();

    const float* Kbh = K + ((size_t)b * LL * HH + h) * EE;   // + cj*H*E
    const float* Vbh = V + ((size_t)b * LL * HH + h) * DD;   // + cj*H*D

    // ---- score phase: 8 lanes per key, 4 keys per iteration ----
    const int grp = lane >> 3;     // key within quad
    const int sub = lane & 7;      // 16B chunk within each 128B half-row
    const float4 q0 = *(const float4*)&sq[warp][sub * 4];
    const float4 q1 = *(const float4*)&sq[warp][32 + sub * 4];

    float s = -INFINITY;
#pragma unroll
    for (int jb = 0; jb < 6; ++jb) {
        int j  = jb * 4 + grp;
        int cj = col_of(l, j);
        const float4* kp = (const float4*)(Kbh + (size_t)cj * (HH * EE));
        float4 k0 = kp[sub];        // line 0 of this K row (coalesced per 8-lane group)
        float4 k1 = kp[8 + sub];    // line 1
        float part = q0.x*k0.x + q0.y*k0.y + q0.z*k0.z + q0.w*k0.w
                   + q1.x*k1.x + q1.y*k1.y + q1.z*k1.z + q1.w*k1.w;
        part += __shfl_xor_sync(FULL, part, 1);
        part += __shfl_xor_sync(FULL, part, 2);
        part += __shfl_xor_sync(FULL, part, 4);   // all 8 lanes of group hold s_j
        float v = __shfl_sync(FULL, part, (lane & 3) << 3);
        if ((lane >> 2) == jb) s = v;             // lane j now holds s_j
    }
    if (!act_of(l, lane)) s = -INFINITY;

    // ---- warp softmax over <=22 slots ----
    float m = s;
#pragma unroll
    for (int o = 16; o; o >>= 1) m = fmaxf(m, __shfl_xor_sync(FULL, m, o));
    float p = __expf(s - m);                      // -inf -> 0
    float sum = p;
#pragma unroll
    for (int o = 16; o; o >>= 1) sum += __shfl_xor_sync(FULL, sum, o);
    p *= __frcp_rn(sum);

    // ---- V phase: 16 lanes per key, 2 keys per iteration ----
    const int kp2 = lane >> 4;     // key parity within pair
    const int dl  = lane & 15;     // float4 chunk of the 64-dim output
    float4 acc = make_float4(0.f, 0.f, 0.f, 0.f);
#pragma unroll
    for (int it = 0; it < 11; ++it) {
        int j   = it * 2 + kp2;
        float pj = __shfl_sync(FULL, p, j);       // p_j lives in lane j
        int cj  = col_of(l, j);
        const float4* vp = (const float4*)(Vbh + (size_t)cj * (HH * DD));
        float4 vv = vp[dl];                       // 2 lines per 16-lane group
        acc.x = fmaf(pj, vv.x, acc.x);
        acc.y = fmaf(pj, vv.y, acc.y);
        acc.z = fmaf(pj, vv.z, acc.z);
        acc.w = fmaf(pj, vv.w, acc.w);
    }
    // combine even/odd key halves (lanes t and t+16 hold same dims)
    acc.x += __shfl_xor_sync(FULL, acc.x, 16);
    acc.y += __shfl_xor_sync(FULL, acc.y, 16);
    acc.z += __shfl_xor_sync(FULL, acc.z, 16);
    acc.w += __shfl_xor_sync(FULL, acc.w, 16);

    if (lane < 16)
        ((float4*)(O + (size_t)row * DD))[dl] = acc;
}

extern "C" void kernel_launch(void* const* d_in, const int* in_sizes, int n_in,
                              void* d_out, int out_size) {
    const float* Q = (const float*)d_in[0];
    const float* K = (const float*)d_in[1];
    const float* V = (const float*)d_in[2];
    float* O = (float*)d_out;

    const int total_rows = BB * LL * HH;   // 32768 warps
    dim3 grid(total_rows / 8);             // 8 warps per block
    logsparse_attn_kernel<<<grid, 256>>>(Q, K, V, O);
}

// round 3
// speedup vs baseline: 2.4048x; 1.0263x over previous
#include <cuda_runtime.h>
#include <math.h>

// LogSparseAttention: B=2, L=S=2048, H=8, E=D=64.
// Mask: row l<22 attends cols 0..l; row l>=22 attends {l-10..l} U {l-10-2^i, i=0..10, >=0}.
// <=22 keys per query row -> gather attention, line-coalesced.
// R3: 64-reg budget for MLP, V rows prefetched into registers before the softmax
//     (softmax shuffle chain hides V load latency), 32-bit address math.

#define BB 2
#define LL 2048
#define HH 8
#define EE 64
#define DD 64
#define QSCALE 0.125f
#define FULL 0xffffffffu

__device__ __forceinline__ int col_of(int l, int j) {
    int c;
    if (l < 22) {
        c = (j <= l) ? j : 0;
    } else if (j <= 10) {
        c = l - 10 - (1 << ((10 - j) & 31));
        c = (c >= 0) ? c : 0;
    } else if (j <= 21) {
        c = l - 21 + j;
    } else {
        c = 0;
    }
    return c;
}

__device__ __forceinline__ bool act_of(int l, int j) {
    if (j > 21) return false;
    if (l < 22) return j <= l;
    if (j <= 10) return (l - 10 - (1 << ((10 - j) & 31))) >= 0;
    return true;
}

__global__ __launch_bounds__(256, 4)
void logsparse_attn_kernel(const float* __restrict__ Q,
                           const float* __restrict__ K,
                           const float* __restrict__ V,
                           float* __restrict__ O)
{
    __shared__ float sq[8][EE];

    const int warp = threadIdx.x >> 5;
    const int lane = threadIdx.x & 31;
    const int row  = blockIdx.x * 8 + warp;      // (b*L + l)*H + h
    const int b    = row / (LL * HH);
    const int rem  = row - b * (LL * HH);
    const int l    = rem / HH;
    const int h    = rem - l * HH;

    // stage scaled q
    const float* qrow = Q + row * EE;            // 32-bit offsets: max 2.1M elems
    sq[warp][lane]      = qrow[lane]      * QSCALE;
    sq[warp][lane + 32] = qrow[lane + 32] * QSCALE;
    __syncwarp();

    const float* Kbh = K + (b * (LL * HH) + h) * EE;
    const float* Vbh = V + (b * (LL * HH) + h) * DD;

    // ---- score phase: 8 lanes/key, 4 keys/iter, 6 iters (24 >= 22 slots) ----
    const int grp = lane >> 3;
    const int sub = lane & 7;
    const float4 q0 = *(const float4*)&sq[warp][sub * 4];
    const float4 q1 = *(const float4*)&sq[warp][32 + sub * 4];

    float s = -INFINITY;
#pragma unroll
    for (int jb = 0; jb < 6; ++jb) {
        int j  = jb * 4 + grp;
        int cj = col_of(l, j);
        const float4* kp = (const float4*)(Kbh + cj * (HH * EE));
        float4 k0 = kp[sub];
        float4 k1 = kp[8 + sub];
        float part = q0.x*k0.x + q0.y*k0.y + q0.z*k0.z + q0.w*k0.w
                   + q1.x*k1.x + q1.y*k1.y + q1.z*k1.z + q1.w*k1.w;
        part += __shfl_xor_sync(FULL, part, 1);
        part += __shfl_xor_sync(FULL, part, 2);
        part += __shfl_xor_sync(FULL, part, 4);
        float v = __shfl_sync(FULL, part, (lane & 3) << 3);
        if ((lane >> 2) == jb) s = v;            // lane j holds s_j
    }
    if (!act_of(l, lane)) s = -INFINITY;

    // ---- prefetch all V rows into registers (independent of softmax) ----
    const int kp2 = lane >> 4;                   // key parity within pair
    const int dl  = lane & 15;                   // float4 chunk of 64-dim row
    float4 vv[11];
#pragma unroll
    for (int it = 0; it < 11; ++it) {
        int j  = it * 2 + kp2;
        int cj = col_of(l, j);
        vv[it] = ((const float4*)(Vbh + cj * (HH * DD)))[dl];
    }

    // ---- warp softmax (shuffle chain hides the V loads above) ----
    float m = s;
#pragma unroll
    for (int o = 16; o; o >>= 1) m = fmaxf(m, __shfl_xor_sync(FULL, m, o));
    float p = __expf(s - m);                     // -inf -> 0
    float sum = p;
#pragma unroll
    for (int o = 16; o; o >>= 1) sum += __shfl_xor_sync(FULL, sum, o);
    p *= __frcp_rn(sum);

    // ---- weighted accumulation ----
    float4 acc = make_float4(0.f, 0.f, 0.f, 0.f);
#pragma unroll
    for (int it = 0; it < 11; ++it) {
        float pj = __shfl_sync(FULL, p, it * 2 + kp2);
        acc.x = fmaf(pj, vv[it].x, acc.x);
        acc.y = fmaf(pj, vv[it].y, acc.y);
        acc.z = fmaf(pj, vv[it].z, acc.z);
        acc.w = fmaf(pj, vv[it].w, acc.w);
    }
    acc.x += __shfl_xor_sync(FULL, acc.x, 16);
    acc.y += __shfl_xor_sync(FULL, acc.y, 16);
    acc.z += __shfl_xor_sync(FULL, acc.z, 16);
    acc.w += __shfl_xor_sync(FULL, acc.w, 16);

    if (lane < 16)
        ((float4*)(O + row * DD))[dl] = acc;
}

extern "C" void kernel_launch(void* const* d_in, const int* in_sizes, int n_in,
                              void* d_out, int out_size) {
    const float* Q = (const float*)d_in[0];
    const float* K = (const float*)d_in[1];
    const float* V = (const float*)d_in[2];
    float* O = (float*)d_out;

    const int total_rows = BB * LL * HH;   // 32768 warps
    dim3 grid(total_rows / 8);
    logsparse_attn_kernel<<<grid, 256>>>(Q, K, V, O);
}